// round 11
// baseline (speedup 1.0000x reference)
#include <cuda_runtime.h>
#include <stdint.h>

// ---------------------------------------------------------------------------
// Problem constants
// ---------------------------------------------------------------------------
#define T_TOK 2048
#define HS    768
#define P_EXP 8
#define M_SUB 1024
#define D_EMB 512

#define OFF_WORD 0
#define OFF_PSR  (T_TOK)
#define OFF_ATK  (OFF_PSR + T_TOK * D_EMB)
#define OFF_ENT  (OFF_ATK + T_TOK * D_EMB)
#define OFF_CPY  (OFF_ENT + 1)
#define OFF_OBF  (OFF_CPY + T_TOK)
#define OFF_PRI  (OFF_OBF + T_TOK)

// MMA tiling
#define TBM 32
#define TBN 64
#define TBK 16
#define STG 4
#define ARS 20       // A smem row stride (floats)
#define BRS 72       // B smem row stride (floats)

// ---------------------------------------------------------------------------
// Device scratch (split-K partial buffers)
// ---------------------------------------------------------------------------
__device__ float g_spt_a[(size_t)T_TOK * M_SUB];
__device__ float g_spt_b[(size_t)T_TOK * M_SUB];
__device__ float g_spt[(size_t)T_TOK * M_SUB];    // final spt (written by K2)
__device__ float g_pa[(size_t)T_TOK * M_SUB];     // gemm1 partial kz=0 (psr|atk)
__device__ float g_pb[(size_t)T_TOK * M_SUB];     // gemm1 partial kz=1
__device__ int   g_cnt[P_EXP];
__device__ int   g_list[P_EXP][T_TOK];
__device__ float g_negent[T_TOK];

// ---------------------------------------------------------------------------
// helpers
// ---------------------------------------------------------------------------
// Truncation-based tf32 split: hi = top 19 bits (exactly what the tensor core
// reads from an fp32 register), lo = exact residual. No cvt instructions:
// 1 LOP3 + 1 FSUB per split. The lo operand is passed raw (HW truncates it;
// the dropped bits contribute ~2^-24 relative error).
__device__ __forceinline__ void split2(float v, uint32_t& hi, uint32_t& lo) {
    uint32_t h = __float_as_uint(v) & 0xffffe000u;
    hi = h;
    lo = __float_as_uint(v - __uint_as_float(h));
}
__device__ __forceinline__ void mma_tf32(float* d, uint32_t a0, uint32_t a1,
                                         uint32_t a2, uint32_t a3,
                                         uint32_t b0, uint32_t b1) {
    asm volatile(
        "mma.sync.aligned.m16n8k8.row.col.f32.tf32.tf32.f32 "
        "{%0,%1,%2,%3}, {%4,%5,%6,%7}, {%8,%9}, {%0,%1,%2,%3};\n"
        : "+f"(d[0]), "+f"(d[1]), "+f"(d[2]), "+f"(d[3])
        : "r"(a0), "r"(a1), "r"(a2), "r"(a3), "r"(b0), "r"(b1));
}
__device__ __forceinline__ void cp16(uint32_t dst, const void* src, uint32_t sz) {
    asm volatile("cp.async.cg.shared.global [%0], [%1], 16, %2;\n"
                 :: "r"(dst), "l"(src), "r"(sz));
}
__device__ __forceinline__ void cp_commit() {
    asm volatile("cp.async.commit_group;\n" ::);
}
__device__ __forceinline__ void cp_wait2() {
    asm volatile("cp.async.wait_group 2;\n" ::: "memory");
}

// ---------------------------------------------------------------------------
// K0: compact token indices per expert
// ---------------------------------------------------------------------------
__global__ void k0_compact(const int* __restrict__ inp_pos) {
    int tid = threadIdx.x;
    if (tid < P_EXP) g_cnt[tid] = 0;
    __syncthreads();
    for (int t = tid; t < T_TOK; t += blockDim.x) {
        int p = inp_pos[t];
        if (p < P_EXP) {
            int slot = atomicAdd(&g_cnt[p], 1);
            g_list[p][slot] = t;
        }
    }
}

// ---------------------------------------------------------------------------
// Tensor GEMM: 3xTF32 (truncation split), 4-stage cp.async, split-K=2.
// MODE 0: partial logits (no bias)   A=ctx[T,768],  B=dec_W
// MODE 1: partial embedding mix      A=spt[T,1024], B=gathered emb rows
// Block 32x64, 128 threads (4 warps, 2x2 of m16n32).
// ---------------------------------------------------------------------------
template <int MODE>
__global__ __launch_bounds__(128) void gemm_mma(
    const float* __restrict__ A_in,
    const float* __restrict__ B0,      // dec_W | psr_w
    const float* __restrict__ B1,      // -     | atk_w
    const int*   __restrict__ words,
    float*       __restrict__ out_a,   // partial kz=0
    float*       __restrict__ out_b)   // partial kz=1
{
    const int pz = blockIdx.z;
    const int p  = pz >> 1;
    const int kz = pz & 1;
    const int mt = blockIdx.y;
    const int nt = blockIdx.x;
    const int cnt = g_cnt[p];
    if (mt * TBM >= cnt) return;

    constexpr int KDIM = (MODE == 0) ? HS : M_SUB;
    constexpr int KH   = KDIM / 2;
    constexpr int NIT  = KH / TBK;
    const int kbeg = kz * KH;

    __shared__ int toks[TBM];
    __shared__ __align__(16) float As[STG][TBM][ARS];
    __shared__ __align__(16) float Bs[STG][TBK][BRS];

    const int tid = threadIdx.x;
    if (tid < TBM) {
        int r = mt * TBM + tid;
        toks[tid] = (r < cnt) ? g_list[p][r] : -1;
    }
    __syncthreads();

    // loader roles
    const int am = tid >> 2;
    const int aq = tid & 3;
    const int br = tid >> 3;
    const int bc = tid & 7;

    const int atok = toks[am];
    const float* Arow = A_in + (size_t)(atok < 0 ? 0 : atok) * KDIM + kbeg;

    const float* Bp = nullptr;
    const float* tab = nullptr;
    const int* wp = nullptr;
    int dbase = 0;
    if (MODE == 0) {
        Bp = B0 + (size_t)p * HS * M_SUB + (size_t)kbeg * M_SUB + nt * TBN;
    } else {
        const int cbase0 = nt * TBN;
        tab   = (cbase0 < D_EMB) ? B0 : B1;
        dbase = (cbase0 < D_EMB) ? cbase0 : (cbase0 - D_EMB);
        wp    = words + p * M_SUB + kbeg;
    }

    const uint32_t sA = (uint32_t)__cvta_generic_to_shared(&As[0][0][0]);
    const uint32_t sB = (uint32_t)__cvta_generic_to_shared(&Bs[0][0][0]);
    const uint32_t aOK = (atok >= 0) ? 16u : 0u;
    const uint32_t adst = (uint32_t)(am * ARS + aq * 4) * 4u;
    const uint32_t bdst0 = (uint32_t)(br * BRS + bc * 4) * 4u;
    const uint32_t bdst1 = bdst0 + 128u;

    auto issue_stage = [&](int s, int k0) {
        cp16(sA + s * (TBM * ARS * 4) + adst, Arow + k0 + aq * 4, aOK);
        if (MODE == 0) {
            const float* row = Bp + (size_t)(k0 + br) * M_SUB;
            cp16(sB + s * (TBK * BRS * 4) + bdst0, row + bc * 4, 16);
            cp16(sB + s * (TBK * BRS * 4) + bdst1, row + (bc + 8) * 4, 16);
        } else {
            int w = __ldg(&wp[k0 + br]);
            const float* row = tab + (size_t)w * D_EMB + dbase;
            cp16(sB + s * (TBK * BRS * 4) + bdst0, row + bc * 4, 16);
            cp16(sB + s * (TBK * BRS * 4) + bdst1, row + (bc + 8) * 4, 16);
        }
        cp_commit();
    };

    // compute coordinates
    const int lane = tid & 31;
    const int wid  = tid >> 5;
    const int g = lane >> 2;
    const int t = lane & 3;
    const int r0w = (wid & 1) * 16;
    const int c0w = (wid >> 1) * 32;
    const int ra0 = r0w + g, ra1 = r0w + g + 8;

    float d[4][4] = {};

    issue_stage(0, 0);
    issue_stage(1, TBK);
    issue_stage(2, 2 * TBK);

    for (int it = 0; it < NIT; it++) {
        const int cur = it & (STG - 1);
        cp_wait2();
        __syncthreads();

        #pragma unroll
        for (int ko8 = 0; ko8 < 2; ko8++) {
            const int kk = ko8 * 8 + t;
            float af0 = As[cur][ra0][kk];
            float af1 = As[cur][ra1][kk];
            float af2 = As[cur][ra0][kk + 4];
            float af3 = As[cur][ra1][kk + 4];
            uint32_t ah0, al0, ah1, al1, ah2, al2, ah3, al3;
            split2(af0, ah0, al0);
            split2(af1, ah1, al1);
            split2(af2, ah2, al2);
            split2(af3, ah3, al3);
            #pragma unroll
            for (int j = 0; j < 4; j++) {
                const int n = c0w + 8 * j + g;
                float bf0 = Bs[cur][kk][n];
                float bf1 = Bs[cur][kk + 4][n];
                uint32_t bh0, bl0, bh1, bl1;
                split2(bf0, bh0, bl0);
                split2(bf1, bh1, bl1);
                mma_tf32(d[j], ah0, ah1, ah2, ah3, bh0, bh1);
                mma_tf32(d[j], ah0, ah1, ah2, ah3, bl0, bl1);
                mma_tf32(d[j], al0, al1, al2, al3, bh0, bh1);
            }
        }

        if (it + 3 < NIT) issue_stage((it + 3) & (STG - 1), (it + 3) * TBK);
        else cp_commit();
        __syncthreads();
    }

    // epilogue: write partial to the kz-specific buffer (combined col layout)
    float* outp = kz ? out_b : out_a;
    const int tok0 = toks[ra0];
    const int tok1 = toks[ra1];
    #pragma unroll
    for (int j = 0; j < 4; j++) {
        const int gcol = nt * TBN + c0w + 8 * j + 2 * t;
        if (tok0 >= 0)
            *reinterpret_cast<float2*>(&outp[(size_t)tok0 * M_SUB + gcol]) =
                make_float2(d[j][0], d[j][1]);
        if (tok1 >= 0)
            *reinterpret_cast<float2*>(&outp[(size_t)tok1 * M_SUB + gcol]) =
                make_float2(d[j][2], d[j][3]);
    }
}

// ---------------------------------------------------------------------------
// Block reductions (256 threads)
// ---------------------------------------------------------------------------
__device__ __forceinline__ float blockMax256(float v, volatile float* red, int tid) {
    int lane = tid & 31;
    #pragma unroll
    for (int o = 16; o > 0; o >>= 1)
        v = fmaxf(v, __shfl_xor_sync(0xffffffffu, v, o));
    __syncthreads();
    if (lane == 0) red[tid >> 5] = v;
    __syncthreads();
    float r = red[0];
    #pragma unroll
    for (int i = 1; i < 8; i++) r = fmaxf(r, red[i]);
    return r;
}

__device__ __forceinline__ float blockSum256(float v, volatile float* red, int tid) {
    int lane = tid & 31;
    #pragma unroll
    for (int o = 16; o > 0; o >>= 1)
        v += __shfl_xor_sync(0xffffffffu, v, o);
    __syncthreads();
    if (lane == 0) red[tid >> 5] = v;
    __syncthreads();
    float r = red[0];
    #pragma unroll
    for (int i = 1; i < 8; i++) r += red[i];
    return r;
}

__device__ __forceinline__ void blockArgMax256(float& v, int& idx,
                                               volatile float* red, volatile int* redi,
                                               int tid) {
    int lane = tid & 31;
    #pragma unroll
    for (int o = 16; o > 0; o >>= 1) {
        float ov = __shfl_xor_sync(0xffffffffu, v, o);
        int   oi = __shfl_xor_sync(0xffffffffu, idx, o);
        if (ov > v || (ov == v && oi < idx)) { v = ov; idx = oi; }
    }
    __syncthreads();
    if (lane == 0) { red[tid >> 5] = v; redi[tid >> 5] = idx; }
    __syncthreads();
    float bv = red[0]; int bi = redi[0];
    #pragma unroll
    for (int i = 1; i < 8; i++) {
        float ov = red[i]; int oi = redi[i];
        if (ov > bv || (ov == bv && oi < bi)) { bv = ov; bi = oi; }
    }
    v = bv; idx = bi;
}

// ---------------------------------------------------------------------------
// K2: combines logit partials (+bias), then row ops; writes spt
// ---------------------------------------------------------------------------
__global__ __launch_bounds__(256) void k2_row(const int* __restrict__ inp_word,
                                              const int* __restrict__ inp_pos,
                                              const int* __restrict__ inp_mask,
                                              const float* __restrict__ u_gum,
                                              const int* __restrict__ words,
                                              const float* __restrict__ psr_w,
                                              const float* __restrict__ atk_w,
                                              const float* __restrict__ dec_b,
                                              float* __restrict__ out) {
    const int t   = blockIdx.x;
    const int tid = threadIdx.x;
    const int w0  = inp_word[t];
    const int p   = inp_pos[t];
    const bool mk = inp_mask[t] != 0;

    if (p >= P_EXP) {
        if (tid == 0) {
            out[OFF_WORD + t] = (float)w0;
            out[OFF_CPY + t]  = mk ? 1.0f : 0.0f;
            out[OFF_OBF + t]  = 0.0f;
            out[OFF_PRI + t]  = 0.0f;
        }
        const float4* ps = (const float4*)(psr_w + (size_t)w0 * D_EMB);
        const float4* as = (const float4*)(atk_w + (size_t)w0 * D_EMB);
        float4* po = (float4*)(out + OFF_PSR + (size_t)t * D_EMB);
        float4* ao = (float4*)(out + OFF_ATK + (size_t)t * D_EMB);
        for (int d = tid; d < D_EMB / 4; d += 256) { po[d] = ps[d]; ao[d] = as[d]; }
        return;
    }

    __shared__ float red[8];
    __shared__ int   redi[8];

    const float4* av = (const float4*)(g_spt_a + (size_t)t * M_SUB);
    const float4* bv = (const float4*)(g_spt_b + (size_t)t * M_SUB);
    const float4* bb = (const float4*)(dec_b + (size_t)p * M_SUB);
    const float4* uv = (const float4*)(u_gum + (size_t)t * M_SUB);
    float4* rowv = (float4*)(g_spt + (size_t)t * M_SUB);

    float4 pa = av[tid], pb = bv[tid], bi = bb[tid], uu4 = uv[tid];
    float l[4] = {pa.x + pb.x + bi.x, pa.y + pb.y + bi.y,
                  pa.z + pb.z + bi.z, pa.w + pb.w + bi.w};
    float u4[4] = {uu4.x, uu4.y, uu4.z, uu4.w};
    float z[4];
    #pragma unroll
    for (int k = 0; k < 4; k++) {
        float uu = fminf(fmaxf(u4[k], 1e-6f), 1.0f - 1e-6f);
        z[k] = l[k] - logf(-logf(uu));
    }

    float m1 = fmaxf(fmaxf(l[0], l[1]), fmaxf(l[2], l[3]));
    m1 = blockMax256(m1, red, tid);
    float s1 = 0.0f;
    #pragma unroll
    for (int k = 0; k < 4; k++) s1 += expf(l[k] - m1);
    s1 = blockSum256(s1, red, tid);
    const float lse = m1 + logf(s1);

    float se = 0.0f;
    #pragma unroll
    for (int k = 0; k < 4; k++) {
        float ps = l[k] - lse;
        se += ps * expf(ps);
    }
    se = blockSum256(se, red, tid);
    if (tid == 0) g_negent[t] = -se;

    float mv = z[0]; int midx = tid * 4;
    #pragma unroll
    for (int k = 1; k < 4; k++) {
        if (z[k] > mv) { mv = z[k]; midx = tid * 4 + k; }
    }
    blockArgMax256(mv, midx, red, redi, tid);

    float s2 = 0.0f;
    #pragma unroll
    for (int k = 0; k < 4; k++) s2 += expf(z[k] - mv);
    s2 = blockSum256(s2, red, tid);
    const float inv = 1.0f / s2;
    float4 sv;
    sv.x = expf(z[0] - mv) * inv;
    sv.y = expf(z[1] - mv) * inv;
    sv.z = expf(z[2] - mv) * inv;
    sv.w = expf(z[3] - mv) * inv;
    rowv[tid] = sv;

    if (tid == 0) {
        int aw = words[p * M_SUB + midx];
        out[OFF_WORD + t] = (float)aw;
        out[OFF_CPY + t]  = (aw == w0 && mk) ? 1.0f : 0.0f;
        out[OFF_OBF + t]  = 1.0f;
        out[OFF_PRI + t]  = (p < 4) ? 1.0f : 0.0f;
    }
}

// ---------------------------------------------------------------------------
// K5: combine gemm<1> partials into out (target tokens only)
// ---------------------------------------------------------------------------
__global__ __launch_bounds__(256) void k5_combine(const int* __restrict__ inp_pos,
                                                  float* __restrict__ out) {
    const int t = blockIdx.x;
    if (inp_pos[t] >= P_EXP) return;
    const int tid = threadIdx.x;   // 256 threads, 1 float4 each over 1024 cols
    const float4 va = ((const float4*)(g_pa + (size_t)t * M_SUB))[tid];
    const float4 vb = ((const float4*)(g_pb + (size_t)t * M_SUB))[tid];
    float4 v = make_float4(va.x + vb.x, va.y + vb.y, va.z + vb.z, va.w + vb.w);
    const int col = tid * 4;
    if (col < D_EMB)
        *((float4*)(out + OFF_PSR + (size_t)t * D_EMB + col)) = v;
    else
        *((float4*)(out + OFF_ATK + (size_t)t * D_EMB + col - D_EMB)) = v;
}

// ---------------------------------------------------------------------------
// K4: deterministic entropy finalize
// ---------------------------------------------------------------------------
__global__ void k4_ent(const int* __restrict__ inp_pos, float* __restrict__ out) {
    __shared__ float sh[256];
    __shared__ int   shc[256];
    __shared__ float ent_s;
    const int tid = threadIdx.x;
    if (tid == 0) ent_s = 0.0f;

    for (int p = 0; p < P_EXP; p++) {
        float s = 0.0f; int c = 0;
        for (int t = tid; t < T_TOK; t += 256) {
            if (inp_pos[t] == p) { s += g_negent[t]; c++; }
        }
        sh[tid] = s; shc[tid] = c;
        __syncthreads();
        for (int o = 128; o > 0; o >>= 1) {
            if (tid < o) { sh[tid] += sh[tid + o]; shc[tid] += shc[tid + o]; }
            __syncthreads();
        }
        if (tid == 0 && shc[0] > 0)
            ent_s += sh[0] / ((float)shc[0] * (float)M_SUB);
        __syncthreads();
    }
    if (tid == 0) out[OFF_ENT] = -ent_s;
}

// ---------------------------------------------------------------------------
// Entry point
// ---------------------------------------------------------------------------
extern "C" void kernel_launch(void* const* d_in, const int* in_sizes, int n_in,
                              void* d_out, int out_size) {
    const int*      inp_word = (const int*)d_in[0];
    const int*      inp_pos  = (const int*)d_in[1];
    const int*      inp_mask = (const int*)d_in[2];   // JAX bool -> int32
    const float*    ctx      = (const float*)d_in[3];
    const float*    dec_W    = (const float*)d_in[4];
    const float*    dec_b    = (const float*)d_in[5];
    const float*    psr_w    = (const float*)d_in[6];
    const float*    atk_w    = (const float*)d_in[7];
    const int*      words    = (const int*)d_in[8];
    const float*    u_gum    = (const float*)d_in[9];
    float*          out      = (float*)d_out;

    (void)in_sizes; (void)n_in; (void)out_size;

    static float* spt_ptr = nullptr;
    static float* spt_a = nullptr;
    static float* spt_b = nullptr;
    static float* pa = nullptr;
    static float* pb = nullptr;
    if (spt_ptr == nullptr) {
        cudaGetSymbolAddress((void**)&spt_ptr, g_spt);
        cudaGetSymbolAddress((void**)&spt_a, g_spt_a);
        cudaGetSymbolAddress((void**)&spt_b, g_spt_b);
        cudaGetSymbolAddress((void**)&pa, g_pa);
        cudaGetSymbolAddress((void**)&pb, g_pb);
    }

    k0_compact<<<1, 256>>>(inp_pos);
    gemm_mma<0><<<dim3(M_SUB / TBN, T_TOK / TBM, P_EXP * 2), 128>>>(
        ctx, dec_W, nullptr, words, spt_a, spt_b);
    k2_row<<<T_TOK, 256>>>(inp_word, inp_pos, inp_mask, u_gum, words,
                           psr_w, atk_w, dec_b, out);
    gemm_mma<1><<<dim3((2 * D_EMB) / TBN, T_TOK / TBM, P_EXP * 2), 128>>>(
        spt_ptr, psr_w, atk_w, words, pa, pb);
    k5_combine<<<T_TOK, 256>>>(inp_pos, out);
    k4_ent<<<1, 256>>>(inp_pos, out);
}

// round 12
// speedup vs baseline: 1.2322x; 1.2322x over previous
#include <cuda_runtime.h>
#include <stdint.h>

// ---------------------------------------------------------------------------
// Problem constants
// ---------------------------------------------------------------------------
#define T_TOK 2048
#define HS    768
#define P_EXP 8
#define M_SUB 1024
#define D_EMB 512

#define OFF_WORD 0
#define OFF_PSR  (T_TOK)
#define OFF_ATK  (OFF_PSR + T_TOK * D_EMB)
#define OFF_ENT  (OFF_ATK + T_TOK * D_EMB)
#define OFF_CPY  (OFF_ENT + 1)
#define OFF_OBF  (OFF_CPY + T_TOK)
#define OFF_PRI  (OFF_OBF + T_TOK)

// MMA tiling
#define TBM 32
#define TBN 64
#define TBK 16
#define STG 4
#define SPK 4        // split-K factor
#define ARS 20       // A smem row stride (floats)
#define BRS 72       // B smem row stride (floats)

// ---------------------------------------------------------------------------
// Device scratch (split-K partial buffers, indexed by kz)
// ---------------------------------------------------------------------------
__device__ float g_lg_part[(size_t)SPK * T_TOK * M_SUB];  // logit partials
__device__ float g_em_part[(size_t)SPK * T_TOK * M_SUB];  // embedding partials
__device__ float g_spt[(size_t)T_TOK * M_SUB];            // final spt (K2)
__device__ int   g_cnt[P_EXP];
__device__ int   g_list[P_EXP][T_TOK];
__device__ float g_negent[T_TOK];

// ---------------------------------------------------------------------------
// helpers (cvt-based tf32 split — R10-proven schedule; do not replace)
// ---------------------------------------------------------------------------
__device__ __forceinline__ uint32_t f2tf32(float x) {
    uint32_t r;
    asm("cvt.rna.tf32.f32 %0, %1;" : "=r"(r) : "f"(x));
    return r;
}
__device__ __forceinline__ void split2(float v, uint32_t& hi, uint32_t& lo) {
    hi = f2tf32(v);
    lo = f2tf32(v - __uint_as_float(hi));
}
__device__ __forceinline__ void mma_tf32(float* d, uint32_t a0, uint32_t a1,
                                         uint32_t a2, uint32_t a3,
                                         uint32_t b0, uint32_t b1) {
    asm volatile(
        "mma.sync.aligned.m16n8k8.row.col.f32.tf32.tf32.f32 "
        "{%0,%1,%2,%3}, {%4,%5,%6,%7}, {%8,%9}, {%0,%1,%2,%3};\n"
        : "+f"(d[0]), "+f"(d[1]), "+f"(d[2]), "+f"(d[3])
        : "r"(a0), "r"(a1), "r"(a2), "r"(a3), "r"(b0), "r"(b1));
}
__device__ __forceinline__ void cp16(uint32_t dst, const void* src, uint32_t sz) {
    asm volatile("cp.async.cg.shared.global [%0], [%1], 16, %2;\n"
                 :: "r"(dst), "l"(src), "r"(sz));
}
__device__ __forceinline__ void cp_commit() {
    asm volatile("cp.async.commit_group;\n" ::);
}
__device__ __forceinline__ void cp_wait2() {
    asm volatile("cp.async.wait_group 2;\n" ::: "memory");
}

// ---------------------------------------------------------------------------
// K0: compact token indices per expert
// ---------------------------------------------------------------------------
__global__ void k0_compact(const int* __restrict__ inp_pos) {
    int tid = threadIdx.x;
    if (tid < P_EXP) g_cnt[tid] = 0;
    __syncthreads();
    for (int t = tid; t < T_TOK; t += blockDim.x) {
        int p = inp_pos[t];
        if (p < P_EXP) {
            int slot = atomicAdd(&g_cnt[p], 1);
            g_list[p][slot] = t;
        }
    }
}

// ---------------------------------------------------------------------------
// Tensor GEMM: 3xTF32, 4-stage cp.async, split-K=4 (blockIdx.z = p*4+kz).
// MODE 0: partial logits (no bias)   A=ctx[T,768],  B=dec_W
// MODE 1: partial embedding mix      A=spt[T,1024], B=gathered emb rows
// Block 32x64, 128 threads (4 warps, 2x2 of m16n32).
// ---------------------------------------------------------------------------
template <int MODE>
__global__ __launch_bounds__(128) void gemm_mma(
    const float* __restrict__ A_in,
    const float* __restrict__ B0,      // dec_W | psr_w
    const float* __restrict__ B1,      // -     | atk_w
    const int*   __restrict__ words,
    float*       __restrict__ out_part)
{
    const int pz = blockIdx.z;
    const int p  = pz >> 2;
    const int kz = pz & 3;
    const int mt = blockIdx.y;
    const int nt = blockIdx.x;
    const int cnt = g_cnt[p];
    if (mt * TBM >= cnt) return;

    constexpr int KDIM = (MODE == 0) ? HS : M_SUB;
    constexpr int KH   = KDIM / SPK;     // 192 | 256
    constexpr int NIT  = KH / TBK;       // 12  | 16
    const int kbeg = kz * KH;

    __shared__ int toks[TBM];
    __shared__ __align__(16) float As[STG][TBM][ARS];
    __shared__ __align__(16) float Bs[STG][TBK][BRS];

    const int tid = threadIdx.x;
    if (tid < TBM) {
        int r = mt * TBM + tid;
        toks[tid] = (r < cnt) ? g_list[p][r] : -1;
    }
    __syncthreads();

    // loader roles
    const int am = tid >> 2;
    const int aq = tid & 3;
    const int br = tid >> 3;
    const int bc = tid & 7;

    const int atok = toks[am];
    const float* Arow = A_in + (size_t)(atok < 0 ? 0 : atok) * KDIM + kbeg;

    const float* Bp = nullptr;
    const float* tab = nullptr;
    const int* wp = nullptr;
    int dbase = 0;
    if (MODE == 0) {
        Bp = B0 + (size_t)p * HS * M_SUB + (size_t)kbeg * M_SUB + nt * TBN;
    } else {
        const int cbase0 = nt * TBN;
        tab   = (cbase0 < D_EMB) ? B0 : B1;
        dbase = (cbase0 < D_EMB) ? cbase0 : (cbase0 - D_EMB);
        wp    = words + p * M_SUB + kbeg;
    }

    const uint32_t sA = (uint32_t)__cvta_generic_to_shared(&As[0][0][0]);
    const uint32_t sB = (uint32_t)__cvta_generic_to_shared(&Bs[0][0][0]);
    const uint32_t aOK = (atok >= 0) ? 16u : 0u;
    const uint32_t adst = (uint32_t)(am * ARS + aq * 4) * 4u;
    const uint32_t bdst0 = (uint32_t)(br * BRS + bc * 4) * 4u;
    const uint32_t bdst1 = bdst0 + 128u;

    auto issue_stage = [&](int s, int k0) {
        cp16(sA + s * (TBM * ARS * 4) + adst, Arow + k0 + aq * 4, aOK);
        if (MODE == 0) {
            const float* row = Bp + (size_t)(k0 + br) * M_SUB;
            cp16(sB + s * (TBK * BRS * 4) + bdst0, row + bc * 4, 16);
            cp16(sB + s * (TBK * BRS * 4) + bdst1, row + (bc + 8) * 4, 16);
        } else {
            int w = __ldg(&wp[k0 + br]);
            const float* row = tab + (size_t)w * D_EMB + dbase;
            cp16(sB + s * (TBK * BRS * 4) + bdst0, row + bc * 4, 16);
            cp16(sB + s * (TBK * BRS * 4) + bdst1, row + (bc + 8) * 4, 16);
        }
        cp_commit();
    };

    // compute coordinates
    const int lane = tid & 31;
    const int wid  = tid >> 5;
    const int g = lane >> 2;
    const int t = lane & 3;
    const int r0w = (wid & 1) * 16;
    const int c0w = (wid >> 1) * 32;
    const int ra0 = r0w + g, ra1 = r0w + g + 8;

    float d[4][4] = {};

    issue_stage(0, 0);
    issue_stage(1, TBK);
    issue_stage(2, 2 * TBK);

    for (int it = 0; it < NIT; it++) {
        const int cur = it & (STG - 1);
        cp_wait2();
        __syncthreads();

        #pragma unroll
        for (int ko8 = 0; ko8 < 2; ko8++) {
            const int kk = ko8 * 8 + t;
            float af0 = As[cur][ra0][kk];
            float af1 = As[cur][ra1][kk];
            float af2 = As[cur][ra0][kk + 4];
            float af3 = As[cur][ra1][kk + 4];
            uint32_t ah0, al0, ah1, al1, ah2, al2, ah3, al3;
            split2(af0, ah0, al0);
            split2(af1, ah1, al1);
            split2(af2, ah2, al2);
            split2(af3, ah3, al3);
            #pragma unroll
            for (int j = 0; j < 4; j++) {
                const int n = c0w + 8 * j + g;
                float bf0 = Bs[cur][kk][n];
                float bf1 = Bs[cur][kk + 4][n];
                uint32_t bh0, bl0, bh1, bl1;
                split2(bf0, bh0, bl0);
                split2(bf1, bh1, bl1);
                mma_tf32(d[j], ah0, ah1, ah2, ah3, bh0, bh1);
                mma_tf32(d[j], ah0, ah1, ah2, ah3, bl0, bl1);
                mma_tf32(d[j], al0, al1, al2, al3, bh0, bh1);
            }
        }

        if (it + 3 < NIT) issue_stage((it + 3) & (STG - 1), (it + 3) * TBK);
        else cp_commit();
        __syncthreads();
    }

    // epilogue: write partial to the kz slice (combined column layout)
    float* outp = out_part + (size_t)kz * T_TOK * M_SUB;
    const int tok0 = toks[ra0];
    const int tok1 = toks[ra1];
    #pragma unroll
    for (int j = 0; j < 4; j++) {
        const int gcol = nt * TBN + c0w + 8 * j + 2 * t;
        if (tok0 >= 0)
            *reinterpret_cast<float2*>(&outp[(size_t)tok0 * M_SUB + gcol]) =
                make_float2(d[j][0], d[j][1]);
        if (tok1 >= 0)
            *reinterpret_cast<float2*>(&outp[(size_t)tok1 * M_SUB + gcol]) =
                make_float2(d[j][2], d[j][3]);
    }
}

// ---------------------------------------------------------------------------
// Block reductions (256 threads)
// ---------------------------------------------------------------------------
__device__ __forceinline__ float blockMax256(float v, volatile float* red, int tid) {
    int lane = tid & 31;
    #pragma unroll
    for (int o = 16; o > 0; o >>= 1)
        v = fmaxf(v, __shfl_xor_sync(0xffffffffu, v, o));
    __syncthreads();
    if (lane == 0) red[tid >> 5] = v;
    __syncthreads();
    float r = red[0];
    #pragma unroll
    for (int i = 1; i < 8; i++) r = fmaxf(r, red[i]);
    return r;
}

__device__ __forceinline__ float blockSum256(float v, volatile float* red, int tid) {
    int lane = tid & 31;
    #pragma unroll
    for (int o = 16; o > 0; o >>= 1)
        v += __shfl_xor_sync(0xffffffffu, v, o);
    __syncthreads();
    if (lane == 0) red[tid >> 5] = v;
    __syncthreads();
    float r = red[0];
    #pragma unroll
    for (int i = 1; i < 8; i++) r += red[i];
    return r;
}

__device__ __forceinline__ void blockArgMax256(float& v, int& idx,
                                               volatile float* red, volatile int* redi,
                                               int tid) {
    int lane = tid & 31;
    #pragma unroll
    for (int o = 16; o > 0; o >>= 1) {
        float ov = __shfl_xor_sync(0xffffffffu, v, o);
        int   oi = __shfl_xor_sync(0xffffffffu, idx, o);
        if (ov > v || (ov == v && oi < idx)) { v = ov; idx = oi; }
    }
    __syncthreads();
    if (lane == 0) { red[tid >> 5] = v; redi[tid >> 5] = idx; }
    __syncthreads();
    float bv = red[0]; int bi = redi[0];
    #pragma unroll
    for (int i = 1; i < 8; i++) {
        float ov = red[i]; int oi = redi[i];
        if (ov > bv || (ov == bv && oi < bi)) { bv = ov; bi = oi; }
    }
    v = bv; idx = bi;
}

// ---------------------------------------------------------------------------
// K2: combines 4 logit partials (+bias), then row ops; writes spt
// ---------------------------------------------------------------------------
__global__ __launch_bounds__(256) void k2_row(const int* __restrict__ inp_word,
                                              const int* __restrict__ inp_pos,
                                              const int* __restrict__ inp_mask,
                                              const float* __restrict__ u_gum,
                                              const int* __restrict__ words,
                                              const float* __restrict__ psr_w,
                                              const float* __restrict__ atk_w,
                                              const float* __restrict__ dec_b,
                                              float* __restrict__ out) {
    const int t   = blockIdx.x;
    const int tid = threadIdx.x;
    const int w0  = inp_word[t];
    const int p   = inp_pos[t];
    const bool mk = inp_mask[t] != 0;

    if (p >= P_EXP) {
        if (tid == 0) {
            out[OFF_WORD + t] = (float)w0;
            out[OFF_CPY + t]  = mk ? 1.0f : 0.0f;
            out[OFF_OBF + t]  = 0.0f;
            out[OFF_PRI + t]  = 0.0f;
        }
        const float4* ps = (const float4*)(psr_w + (size_t)w0 * D_EMB);
        const float4* as = (const float4*)(atk_w + (size_t)w0 * D_EMB);
        float4* po = (float4*)(out + OFF_PSR + (size_t)t * D_EMB);
        float4* ao = (float4*)(out + OFF_ATK + (size_t)t * D_EMB);
        for (int d = tid; d < D_EMB / 4; d += 256) { po[d] = ps[d]; ao[d] = as[d]; }
        return;
    }

    __shared__ float red[8];
    __shared__ int   redi[8];

    const float4* bb = (const float4*)(dec_b + (size_t)p * M_SUB);
    const float4* uv = (const float4*)(u_gum + (size_t)t * M_SUB);
    float4* rowv = (float4*)(g_spt + (size_t)t * M_SUB);

    float4 bi = bb[tid], uu4 = uv[tid];
    float l[4] = {bi.x, bi.y, bi.z, bi.w};
    #pragma unroll
    for (int kz = 0; kz < SPK; kz++) {
        const float4 pv = ((const float4*)(g_lg_part +
            (size_t)kz * T_TOK * M_SUB + (size_t)t * M_SUB))[tid];
        l[0] += pv.x; l[1] += pv.y; l[2] += pv.z; l[3] += pv.w;
    }

    float u4[4] = {uu4.x, uu4.y, uu4.z, uu4.w};
    float z[4];
    #pragma unroll
    for (int k = 0; k < 4; k++) {
        float uu = fminf(fmaxf(u4[k], 1e-6f), 1.0f - 1e-6f);
        z[k] = l[k] - logf(-logf(uu));
    }

    float m1 = fmaxf(fmaxf(l[0], l[1]), fmaxf(l[2], l[3]));
    m1 = blockMax256(m1, red, tid);
    float s1 = 0.0f;
    #pragma unroll
    for (int k = 0; k < 4; k++) s1 += expf(l[k] - m1);
    s1 = blockSum256(s1, red, tid);
    const float lse = m1 + logf(s1);

    float se = 0.0f;
    #pragma unroll
    for (int k = 0; k < 4; k++) {
        float ps = l[k] - lse;
        se += ps * expf(ps);
    }
    se = blockSum256(se, red, tid);
    if (tid == 0) g_negent[t] = -se;

    float mv = z[0]; int midx = tid * 4;
    #pragma unroll
    for (int k = 1; k < 4; k++) {
        if (z[k] > mv) { mv = z[k]; midx = tid * 4 + k; }
    }
    blockArgMax256(mv, midx, red, redi, tid);

    float s2 = 0.0f;
    #pragma unroll
    for (int k = 0; k < 4; k++) s2 += expf(z[k] - mv);
    s2 = blockSum256(s2, red, tid);
    const float inv = 1.0f / s2;
    float4 sv;
    sv.x = expf(z[0] - mv) * inv;
    sv.y = expf(z[1] - mv) * inv;
    sv.z = expf(z[2] - mv) * inv;
    sv.w = expf(z[3] - mv) * inv;
    rowv[tid] = sv;

    if (tid == 0) {
        int aw = words[p * M_SUB + midx];
        out[OFF_WORD + t] = (float)aw;
        out[OFF_CPY + t]  = (aw == w0 && mk) ? 1.0f : 0.0f;
        out[OFF_OBF + t]  = 1.0f;
        out[OFF_PRI + t]  = (p < 4) ? 1.0f : 0.0f;
    }
}

// ---------------------------------------------------------------------------
// K5: combine 4 embedding partials into out (target tokens only)
// ---------------------------------------------------------------------------
__global__ __launch_bounds__(256) void k5_combine(const int* __restrict__ inp_pos,
                                                  float* __restrict__ out) {
    const int t = blockIdx.x;
    if (inp_pos[t] >= P_EXP) return;
    const int tid = threadIdx.x;
    float4 v = make_float4(0.f, 0.f, 0.f, 0.f);
    #pragma unroll
    for (int kz = 0; kz < SPK; kz++) {
        const float4 pv = ((const float4*)(g_em_part +
            (size_t)kz * T_TOK * M_SUB + (size_t)t * M_SUB))[tid];
        v.x += pv.x; v.y += pv.y; v.z += pv.z; v.w += pv.w;
    }
    const int col = tid * 4;
    if (col < D_EMB)
        *((float4*)(out + OFF_PSR + (size_t)t * D_EMB + col)) = v;
    else
        *((float4*)(out + OFF_ATK + (size_t)t * D_EMB + col - D_EMB)) = v;
}

// ---------------------------------------------------------------------------
// K4: deterministic entropy finalize
// ---------------------------------------------------------------------------
__global__ void k4_ent(const int* __restrict__ inp_pos, float* __restrict__ out) {
    __shared__ float sh[256];
    __shared__ int   shc[256];
    __shared__ float ent_s;
    const int tid = threadIdx.x;
    if (tid == 0) ent_s = 0.0f;

    for (int p = 0; p < P_EXP; p++) {
        float s = 0.0f; int c = 0;
        for (int t = tid; t < T_TOK; t += 256) {
            if (inp_pos[t] == p) { s += g_negent[t]; c++; }
        }
        sh[tid] = s; shc[tid] = c;
        __syncthreads();
        for (int o = 128; o > 0; o >>= 1) {
            if (tid < o) { sh[tid] += sh[tid + o]; shc[tid] += shc[tid + o]; }
            __syncthreads();
        }
        if (tid == 0 && shc[0] > 0)
            ent_s += sh[0] / ((float)shc[0] * (float)M_SUB);
        __syncthreads();
    }
    if (tid == 0) out[OFF_ENT] = -ent_s;
}

// ---------------------------------------------------------------------------
// Entry point
// ---------------------------------------------------------------------------
extern "C" void kernel_launch(void* const* d_in, const int* in_sizes, int n_in,
                              void* d_out, int out_size) {
    const int*      inp_word = (const int*)d_in[0];
    const int*      inp_pos  = (const int*)d_in[1];
    const int*      inp_mask = (const int*)d_in[2];   // JAX bool -> int32
    const float*    ctx      = (const float*)d_in[3];
    const float*    dec_W    = (const float*)d_in[4];
    const float*    dec_b    = (const float*)d_in[5];
    const float*    psr_w    = (const float*)d_in[6];
    const float*    atk_w    = (const float*)d_in[7];
    const int*      words    = (const int*)d_in[8];
    const float*    u_gum    = (const float*)d_in[9];
    float*          out      = (float*)d_out;

    (void)in_sizes; (void)n_in; (void)out_size;

    static float* spt_ptr = nullptr;
    static float* lg_part = nullptr;
    static float* em_part = nullptr;
    if (spt_ptr == nullptr) {
        cudaGetSymbolAddress((void**)&spt_ptr, g_spt);
        cudaGetSymbolAddress((void**)&lg_part, g_lg_part);
        cudaGetSymbolAddress((void**)&em_part, g_em_part);
    }

    k0_compact<<<1, 256>>>(inp_pos);
    gemm_mma<0><<<dim3(M_SUB / TBN, T_TOK / TBM, P_EXP * SPK), 128>>>(
        ctx, dec_W, nullptr, words, lg_part);
    k2_row<<<T_TOK, 256>>>(inp_word, inp_pos, inp_mask, u_gum, words,
                           psr_w, atk_w, dec_b, out);
    gemm_mma<1><<<dim3((2 * D_EMB) / TBN, T_TOK / TBM, P_EXP * SPK), 128>>>(
        spt_ptr, psr_w, atk_w, words, em_part);
    k5_combine<<<T_TOK, 256>>>(inp_pos, out);
    k4_ent<<<1, 256>>>(inp_pos, out);
}

// round 13
// speedup vs baseline: 1.3337x; 1.0823x over previous
#include <cuda_runtime.h>
#include <stdint.h>

// ---------------------------------------------------------------------------
// Problem constants
// ---------------------------------------------------------------------------
#define T_TOK 2048
#define HS    768
#define P_EXP 8
#define M_SUB 1024
#define D_EMB 512

#define OFF_WORD 0
#define OFF_PSR  (T_TOK)
#define OFF_ATK  (OFF_PSR + T_TOK * D_EMB)
#define OFF_ENT  (OFF_ATK + T_TOK * D_EMB)
#define OFF_CPY  (OFF_ENT + 1)
#define OFF_OBF  (OFF_CPY + T_TOK)
#define OFF_PRI  (OFF_OBF + T_TOK)

// MMA tiling
#define TBM 32
#define TBN 64
#define TBK 16
#define STG 4
#define SPK 4        // split-K factor
#define ARS 20       // A smem row stride (floats)
#define BRS 72       // B smem row stride (floats)
#define MAXT 72      // max tiles: sum_p ceil(cnt_p/32) <= 2048/32 + 8

// ---------------------------------------------------------------------------
// Device scratch
// ---------------------------------------------------------------------------
__device__ float g_lg_part[(size_t)SPK * T_TOK * M_SUB];  // logit partials
__device__ float g_em_part[(size_t)SPK * T_TOK * M_SUB];  // embedding partials
__device__ float g_spt[(size_t)T_TOK * M_SUB];            // final spt (K2)
__device__ int   g_cnt[P_EXP];
__device__ int   g_list[P_EXP][T_TOK];
__device__ int2  g_tiles[MAXT];                           // (p, mt) dense list
__device__ int   g_ntile;
__device__ float g_negent[T_TOK];

// ---------------------------------------------------------------------------
// helpers (cvt-based tf32 split — R10-proven schedule; do not replace)
// ---------------------------------------------------------------------------
__device__ __forceinline__ uint32_t f2tf32(float x) {
    uint32_t r;
    asm("cvt.rna.tf32.f32 %0, %1;" : "=r"(r) : "f"(x));
    return r;
}
__device__ __forceinline__ void split2(float v, uint32_t& hi, uint32_t& lo) {
    hi = f2tf32(v);
    lo = f2tf32(v - __uint_as_float(hi));
}
__device__ __forceinline__ void mma_tf32(float* d, uint32_t a0, uint32_t a1,
                                         uint32_t a2, uint32_t a3,
                                         uint32_t b0, uint32_t b1) {
    asm volatile(
        "mma.sync.aligned.m16n8k8.row.col.f32.tf32.tf32.f32 "
        "{%0,%1,%2,%3}, {%4,%5,%6,%7}, {%8,%9}, {%0,%1,%2,%3};\n"
        : "+f"(d[0]), "+f"(d[1]), "+f"(d[2]), "+f"(d[3])
        : "r"(a0), "r"(a1), "r"(a2), "r"(a3), "r"(b0), "r"(b1));
}
__device__ __forceinline__ void cp16(uint32_t dst, const void* src, uint32_t sz) {
    asm volatile("cp.async.cg.shared.global [%0], [%1], 16, %2;\n"
                 :: "r"(dst), "l"(src), "r"(sz));
}
__device__ __forceinline__ void cp_commit() {
    asm volatile("cp.async.commit_group;\n" ::);
}
__device__ __forceinline__ void cp_wait2() {
    asm volatile("cp.async.wait_group 2;\n" ::: "memory");
}

// ---------------------------------------------------------------------------
// K0: compact token indices per expert + build dense tile list
// ---------------------------------------------------------------------------
__global__ void k0_compact(const int* __restrict__ inp_pos) {
    int tid = threadIdx.x;
    if (tid < P_EXP) g_cnt[tid] = 0;
    __syncthreads();
    for (int t = tid; t < T_TOK; t += blockDim.x) {
        int p = inp_pos[t];
        if (p < P_EXP) {
            int slot = atomicAdd(&g_cnt[p], 1);
            g_list[p][slot] = t;
        }
    }
    __syncthreads();
    if (tid == 0) {
        int n = 0;
        for (int p = 0; p < P_EXP; p++) {
            int c = g_cnt[p];
            for (int mt = 0; mt * TBM < c; mt++)
                g_tiles[n++] = make_int2(p, mt);
        }
        g_ntile = n;
    }
}

// ---------------------------------------------------------------------------
// Tensor GEMM: 3xTF32, 4-stage cp.async, split-K=4, dense tile list.
// grid = (nt=16, tile<=MAXT, kz=SPK)
// MODE 0: partial logits (no bias)   A=ctx[T,768],  B=dec_W
// MODE 1: partial embedding mix      A=spt[T,1024], B=gathered emb rows
// Block 32x64, 128 threads (4 warps, 2x2 of m16n32).
// ---------------------------------------------------------------------------
template <int MODE>
__global__ __launch_bounds__(128) void gemm_mma(
    const float* __restrict__ A_in,
    const float* __restrict__ B0,      // dec_W | psr_w
    const float* __restrict__ B1,      // -     | atk_w
    const int*   __restrict__ words,
    float*       __restrict__ out_part)
{
    const int tix = blockIdx.y;
    if (tix >= g_ntile) return;
    const int2 tile = g_tiles[tix];
    const int p  = tile.x;
    const int mt = tile.y;
    const int kz = blockIdx.z;
    const int nt = blockIdx.x;
    const int cnt = g_cnt[p];

    constexpr int KDIM = (MODE == 0) ? HS : M_SUB;
    constexpr int KH   = KDIM / SPK;     // 192 | 256
    constexpr int NIT  = KH / TBK;       // 12  | 16
    const int kbeg = kz * KH;

    __shared__ int toks[TBM];
    __shared__ __align__(16) float As[STG][TBM][ARS];
    __shared__ __align__(16) float Bs[STG][TBK][BRS];

    const int tid = threadIdx.x;
    if (tid < TBM) {
        int r = mt * TBM + tid;
        toks[tid] = (r < cnt) ? g_list[p][r] : -1;
    }
    __syncthreads();

    // loader roles
    const int am = tid >> 2;
    const int aq = tid & 3;
    const int br = tid >> 3;
    const int bc = tid & 7;

    const int atok = toks[am];
    const float* Arow = A_in + (size_t)(atok < 0 ? 0 : atok) * KDIM + kbeg;

    const float* Bp = nullptr;
    const float* tab = nullptr;
    const int* wp = nullptr;
    int dbase = 0;
    if (MODE == 0) {
        Bp = B0 + (size_t)p * HS * M_SUB + (size_t)kbeg * M_SUB + nt * TBN;
    } else {
        const int cbase0 = nt * TBN;
        tab   = (cbase0 < D_EMB) ? B0 : B1;
        dbase = (cbase0 < D_EMB) ? cbase0 : (cbase0 - D_EMB);
        wp    = words + p * M_SUB + kbeg;
    }

    const uint32_t sA = (uint32_t)__cvta_generic_to_shared(&As[0][0][0]);
    const uint32_t sB = (uint32_t)__cvta_generic_to_shared(&Bs[0][0][0]);
    const uint32_t aOK = (atok >= 0) ? 16u : 0u;
    const uint32_t adst = (uint32_t)(am * ARS + aq * 4) * 4u;
    const uint32_t bdst0 = (uint32_t)(br * BRS + bc * 4) * 4u;
    const uint32_t bdst1 = bdst0 + 128u;

    auto issue_stage = [&](int s, int k0) {
        cp16(sA + s * (TBM * ARS * 4) + adst, Arow + k0 + aq * 4, aOK);
        if (MODE == 0) {
            const float* row = Bp + (size_t)(k0 + br) * M_SUB;
            cp16(sB + s * (TBK * BRS * 4) + bdst0, row + bc * 4, 16);
            cp16(sB + s * (TBK * BRS * 4) + bdst1, row + (bc + 8) * 4, 16);
        } else {
            int w = __ldg(&wp[k0 + br]);
            const float* row = tab + (size_t)w * D_EMB + dbase;
            cp16(sB + s * (TBK * BRS * 4) + bdst0, row + bc * 4, 16);
            cp16(sB + s * (TBK * BRS * 4) + bdst1, row + (bc + 8) * 4, 16);
        }
        cp_commit();
    };

    // compute coordinates
    const int lane = tid & 31;
    const int wid  = tid >> 5;
    const int g = lane >> 2;
    const int t = lane & 3;
    const int r0w = (wid & 1) * 16;
    const int c0w = (wid >> 1) * 32;
    const int ra0 = r0w + g, ra1 = r0w + g + 8;

    float d[4][4] = {};

    issue_stage(0, 0);
    issue_stage(1, TBK);
    issue_stage(2, 2 * TBK);

    for (int it = 0; it < NIT; it++) {
        const int cur = it & (STG - 1);
        cp_wait2();
        __syncthreads();

        #pragma unroll
        for (int ko8 = 0; ko8 < 2; ko8++) {
            const int kk = ko8 * 8 + t;
            float af0 = As[cur][ra0][kk];
            float af1 = As[cur][ra1][kk];
            float af2 = As[cur][ra0][kk + 4];
            float af3 = As[cur][ra1][kk + 4];
            uint32_t ah0, al0, ah1, al1, ah2, al2, ah3, al3;
            split2(af0, ah0, al0);
            split2(af1, ah1, al1);
            split2(af2, ah2, al2);
            split2(af3, ah3, al3);
            #pragma unroll
            for (int j = 0; j < 4; j++) {
                const int n = c0w + 8 * j + g;
                float bf0 = Bs[cur][kk][n];
                float bf1 = Bs[cur][kk + 4][n];
                uint32_t bh0, bl0, bh1, bl1;
                split2(bf0, bh0, bl0);
                split2(bf1, bh1, bl1);
                mma_tf32(d[j], ah0, ah1, ah2, ah3, bh0, bh1);
                mma_tf32(d[j], ah0, ah1, ah2, ah3, bl0, bl1);
                mma_tf32(d[j], al0, al1, al2, al3, bh0, bh1);
            }
        }

        if (it + 3 < NIT) issue_stage((it + 3) & (STG - 1), (it + 3) * TBK);
        else cp_commit();
        __syncthreads();
    }

    // epilogue: write partial to the kz slice (combined column layout)
    float* outp = out_part + (size_t)kz * T_TOK * M_SUB;
    const int tok0 = toks[ra0];
    const int tok1 = toks[ra1];
    #pragma unroll
    for (int j = 0; j < 4; j++) {
        const int gcol = nt * TBN + c0w + 8 * j + 2 * t;
        if (tok0 >= 0)
            *reinterpret_cast<float2*>(&outp[(size_t)tok0 * M_SUB + gcol]) =
                make_float2(d[j][0], d[j][1]);
        if (tok1 >= 0)
            *reinterpret_cast<float2*>(&outp[(size_t)tok1 * M_SUB + gcol]) =
                make_float2(d[j][2], d[j][3]);
    }
}

// ---------------------------------------------------------------------------
// Block reductions (256 threads)
// ---------------------------------------------------------------------------
__device__ __forceinline__ float blockMax256(float v, volatile float* red, int tid) {
    int lane = tid & 31;
    #pragma unroll
    for (int o = 16; o > 0; o >>= 1)
        v = fmaxf(v, __shfl_xor_sync(0xffffffffu, v, o));
    __syncthreads();
    if (lane == 0) red[tid >> 5] = v;
    __syncthreads();
    float r = red[0];
    #pragma unroll
    for (int i = 1; i < 8; i++) r = fmaxf(r, red[i]);
    return r;
}

__device__ __forceinline__ float blockSum256(float v, volatile float* red, int tid) {
    int lane = tid & 31;
    #pragma unroll
    for (int o = 16; o > 0; o >>= 1)
        v += __shfl_xor_sync(0xffffffffu, v, o);
    __syncthreads();
    if (lane == 0) red[tid >> 5] = v;
    __syncthreads();
    float r = red[0];
    #pragma unroll
    for (int i = 1; i < 8; i++) r += red[i];
    return r;
}

__device__ __forceinline__ void blockArgMax256(float& v, int& idx,
                                               volatile float* red, volatile int* redi,
                                               int tid) {
    int lane = tid & 31;
    #pragma unroll
    for (int o = 16; o > 0; o >>= 1) {
        float ov = __shfl_xor_sync(0xffffffffu, v, o);
        int   oi = __shfl_xor_sync(0xffffffffu, idx, o);
        if (ov > v || (ov == v && oi < idx)) { v = ov; idx = oi; }
    }
    __syncthreads();
    if (lane == 0) { red[tid >> 5] = v; redi[tid >> 5] = idx; }
    __syncthreads();
    float bv = red[0]; int bi = redi[0];
    #pragma unroll
    for (int i = 1; i < 8; i++) {
        float ov = red[i]; int oi = redi[i];
        if (ov > bv || (ov == bv && oi < bi)) { bv = ov; bi = oi; }
    }
    v = bv; idx = bi;
}

// ---------------------------------------------------------------------------
// K2: combines 4 logit partials (+bias), then row ops; writes spt
// ---------------------------------------------------------------------------
__global__ __launch_bounds__(256) void k2_row(const int* __restrict__ inp_word,
                                              const int* __restrict__ inp_pos,
                                              const int* __restrict__ inp_mask,
                                              const float* __restrict__ u_gum,
                                              const int* __restrict__ words,
                                              const float* __restrict__ psr_w,
                                              const float* __restrict__ atk_w,
                                              const float* __restrict__ dec_b,
                                              float* __restrict__ out) {
    const int t   = blockIdx.x;
    const int tid = threadIdx.x;
    const int w0  = inp_word[t];
    const int p   = inp_pos[t];
    const bool mk = inp_mask[t] != 0;

    if (p >= P_EXP) {
        if (tid == 0) {
            out[OFF_WORD + t] = (float)w0;
            out[OFF_CPY + t]  = mk ? 1.0f : 0.0f;
            out[OFF_OBF + t]  = 0.0f;
            out[OFF_PRI + t]  = 0.0f;
        }
        const float4* ps = (const float4*)(psr_w + (size_t)w0 * D_EMB);
        const float4* as = (const float4*)(atk_w + (size_t)w0 * D_EMB);
        float4* po = (float4*)(out + OFF_PSR + (size_t)t * D_EMB);
        float4* ao = (float4*)(out + OFF_ATK + (size_t)t * D_EMB);
        for (int d = tid; d < D_EMB / 4; d += 256) { po[d] = ps[d]; ao[d] = as[d]; }
        return;
    }

    __shared__ float red[8];
    __shared__ int   redi[8];

    const float4* bb = (const float4*)(dec_b + (size_t)p * M_SUB);
    const float4* uv = (const float4*)(u_gum + (size_t)t * M_SUB);
    float4* rowv = (float4*)(g_spt + (size_t)t * M_SUB);

    float4 bi = bb[tid], uu4 = uv[tid];
    float l[4] = {bi.x, bi.y, bi.z, bi.w};
    #pragma unroll
    for (int kz = 0; kz < SPK; kz++) {
        const float4 pv = ((const float4*)(g_lg_part +
            (size_t)kz * T_TOK * M_SUB + (size_t)t * M_SUB))[tid];
        l[0] += pv.x; l[1] += pv.y; l[2] += pv.z; l[3] += pv.w;
    }

    float u4[4] = {uu4.x, uu4.y, uu4.z, uu4.w};
    float z[4];
    #pragma unroll
    for (int k = 0; k < 4; k++) {
        float uu = fminf(fmaxf(u4[k], 1e-6f), 1.0f - 1e-6f);
        z[k] = l[k] - logf(-logf(uu));
    }

    float m1 = fmaxf(fmaxf(l[0], l[1]), fmaxf(l[2], l[3]));
    m1 = blockMax256(m1, red, tid);
    float s1 = 0.0f;
    #pragma unroll
    for (int k = 0; k < 4; k++) s1 += expf(l[k] - m1);
    s1 = blockSum256(s1, red, tid);
    const float lse = m1 + logf(s1);

    float se = 0.0f;
    #pragma unroll
    for (int k = 0; k < 4; k++) {
        float ps = l[k] - lse;
        se += ps * expf(ps);
    }
    se = blockSum256(se, red, tid);
    if (tid == 0) g_negent[t] = -se;

    float mv = z[0]; int midx = tid * 4;
    #pragma unroll
    for (int k = 1; k < 4; k++) {
        if (z[k] > mv) { mv = z[k]; midx = tid * 4 + k; }
    }
    blockArgMax256(mv, midx, red, redi, tid);

    float s2 = 0.0f;
    #pragma unroll
    for (int k = 0; k < 4; k++) s2 += expf(z[k] - mv);
    s2 = blockSum256(s2, red, tid);
    const float inv = 1.0f / s2;
    float4 sv;
    sv.x = expf(z[0] - mv) * inv;
    sv.y = expf(z[1] - mv) * inv;
    sv.z = expf(z[2] - mv) * inv;
    sv.w = expf(z[3] - mv) * inv;
    rowv[tid] = sv;

    if (tid == 0) {
        int aw = words[p * M_SUB + midx];
        out[OFF_WORD + t] = (float)aw;
        out[OFF_CPY + t]  = (aw == w0 && mk) ? 1.0f : 0.0f;
        out[OFF_OBF + t]  = 1.0f;
        out[OFF_PRI + t]  = (p < 4) ? 1.0f : 0.0f;
    }
}

// ---------------------------------------------------------------------------
// K5: combine 4 embedding partials into out (target tokens only)
// ---------------------------------------------------------------------------
__global__ __launch_bounds__(256) void k5_combine(const int* __restrict__ inp_pos,
                                                  float* __restrict__ out) {
    const int t = blockIdx.x;
    if (inp_pos[t] >= P_EXP) return;
    const int tid = threadIdx.x;
    float4 v = make_float4(0.f, 0.f, 0.f, 0.f);
    #pragma unroll
    for (int kz = 0; kz < SPK; kz++) {
        const float4 pv = ((const float4*)(g_em_part +
            (size_t)kz * T_TOK * M_SUB + (size_t)t * M_SUB))[tid];
        v.x += pv.x; v.y += pv.y; v.z += pv.z; v.w += pv.w;
    }
    const int col = tid * 4;
    if (col < D_EMB)
        *((float4*)(out + OFF_PSR + (size_t)t * D_EMB + col)) = v;
    else
        *((float4*)(out + OFF_ATK + (size_t)t * D_EMB + col - D_EMB)) = v;
}

// ---------------------------------------------------------------------------
// K4: deterministic entropy finalize
// ---------------------------------------------------------------------------
__global__ void k4_ent(const int* __restrict__ inp_pos, float* __restrict__ out) {
    __shared__ float sh[256];
    __shared__ int   shc[256];
    __shared__ float ent_s;
    const int tid = threadIdx.x;
    if (tid == 0) ent_s = 0.0f;

    for (int p = 0; p < P_EXP; p++) {
        float s = 0.0f; int c = 0;
        for (int t = tid; t < T_TOK; t += 256) {
            if (inp_pos[t] == p) { s += g_negent[t]; c++; }
        }
        sh[tid] = s; shc[tid] = c;
        __syncthreads();
        for (int o = 128; o > 0; o >>= 1) {
            if (tid < o) { sh[tid] += sh[tid + o]; shc[tid] += shc[tid + o]; }
            __syncthreads();
        }
        if (tid == 0 && shc[0] > 0)
            ent_s += sh[0] / ((float)shc[0] * (float)M_SUB);
        __syncthreads();
    }
    if (tid == 0) out[OFF_ENT] = -ent_s;
}

// ---------------------------------------------------------------------------
// Entry point
// ---------------------------------------------------------------------------
extern "C" void kernel_launch(void* const* d_in, const int* in_sizes, int n_in,
                              void* d_out, int out_size) {
    const int*      inp_word = (const int*)d_in[0];
    const int*      inp_pos  = (const int*)d_in[1];
    const int*      inp_mask = (const int*)d_in[2];   // JAX bool -> int32
    const float*    ctx      = (const float*)d_in[3];
    const float*    dec_W    = (const float*)d_in[4];
    const float*    dec_b    = (const float*)d_in[5];
    const float*    psr_w    = (const float*)d_in[6];
    const float*    atk_w    = (const float*)d_in[7];
    const int*      words    = (const int*)d_in[8];
    const float*    u_gum    = (const float*)d_in[9];
    float*          out      = (float*)d_out;

    (void)in_sizes; (void)n_in; (void)out_size;

    static float* spt_ptr = nullptr;
    static float* lg_part = nullptr;
    static float* em_part = nullptr;
    if (spt_ptr == nullptr) {
        cudaGetSymbolAddress((void**)&spt_ptr, g_spt);
        cudaGetSymbolAddress((void**)&lg_part, g_lg_part);
        cudaGetSymbolAddress((void**)&em_part, g_em_part);
    }

    k0_compact<<<1, 256>>>(inp_pos);
    gemm_mma<0><<<dim3(M_SUB / TBN, MAXT, SPK), 128>>>(
        ctx, dec_W, nullptr, words, lg_part);
    k2_row<<<T_TOK, 256>>>(inp_word, inp_pos, inp_mask, u_gum, words,
                           psr_w, atk_w, dec_b, out);
    gemm_mma<1><<<dim3((2 * D_EMB) / TBN, MAXT, SPK), 128>>>(
        spt_ptr, psr_w, atk_w, words, em_part);
    k5_combine<<<T_TOK, 256>>>(inp_pos, out);
    k4_ent<<<1, 256>>>(inp_pos, out);
}

// round 14
// speedup vs baseline: 1.4401x; 1.0798x over previous
#include <cuda_runtime.h>
#include <stdint.h>

// ---------------------------------------------------------------------------
// Problem constants
// ---------------------------------------------------------------------------
#define T_TOK 2048
#define HS    768
#define P_EXP 8
#define M_SUB 1024
#define D_EMB 512

#define OFF_WORD 0
#define OFF_PSR  (T_TOK)
#define OFF_ATK  (OFF_PSR + T_TOK * D_EMB)
#define OFF_ENT  (OFF_ATK + T_TOK * D_EMB)
#define OFF_CPY  (OFF_ENT + 1)
#define OFF_OBF  (OFF_CPY + T_TOK)
#define OFF_PRI  (OFF_OBF + T_TOK)

// MMA tiling
#define TBM 32
#define TBN 64
#define TBK 16
#define STG 4
#define SPK 4        // split-K factor
#define ARS 20       // A smem row stride (floats)
#define BRS 72       // B smem row stride (floats)
#define MAXT 72      // max tiles: sum_p ceil(cnt_p/32) <= 2048/32 + 8

// ---------------------------------------------------------------------------
// Device scratch
// ---------------------------------------------------------------------------
__device__ float g_lg_part[(size_t)SPK * T_TOK * M_SUB];  // logit partials
__device__ float g_em_part[(size_t)SPK * T_TOK * M_SUB];  // embedding partials
__device__ float g_spt[(size_t)T_TOK * M_SUB];            // final spt (K2)
__device__ int   g_cnt[P_EXP];
__device__ int   g_list[P_EXP][T_TOK];
__device__ int2  g_tiles[MAXT];                           // (p, mt) dense list
__device__ int   g_ntile;
__device__ float g_negent[T_TOK];

// ---------------------------------------------------------------------------
// helpers
// ---------------------------------------------------------------------------
__device__ __forceinline__ uint32_t f2tf32(float x) {
    uint32_t r;
    asm("cvt.rna.tf32.f32 %0, %1;" : "=r"(r) : "f"(x));
    return r;
}
// hi: rna-rounded tf32 (R10/R13-proven). lo: RAW residual — the tensor core
// reads the top 19 bits of the fp32 register, so the explicit second cvt is
// redundant; HW truncation of the residual adds only ~2^-24 relative error.
__device__ __forceinline__ void split2(float v, uint32_t& hi, uint32_t& lo) {
    hi = f2tf32(v);
    lo = __float_as_uint(v - __uint_as_float(hi));
}
__device__ __forceinline__ void mma_tf32(float* d, uint32_t a0, uint32_t a1,
                                         uint32_t a2, uint32_t a3,
                                         uint32_t b0, uint32_t b1) {
    asm volatile(
        "mma.sync.aligned.m16n8k8.row.col.f32.tf32.tf32.f32 "
        "{%0,%1,%2,%3}, {%4,%5,%6,%7}, {%8,%9}, {%0,%1,%2,%3};\n"
        : "+f"(d[0]), "+f"(d[1]), "+f"(d[2]), "+f"(d[3])
        : "r"(a0), "r"(a1), "r"(a2), "r"(a3), "r"(b0), "r"(b1));
}
__device__ __forceinline__ void cp16(uint32_t dst, const void* src, uint32_t sz) {
    asm volatile("cp.async.cg.shared.global [%0], [%1], 16, %2;\n"
                 :: "r"(dst), "l"(src), "r"(sz));
}
__device__ __forceinline__ void cp_commit() {
    asm volatile("cp.async.commit_group;\n" ::);
}
__device__ __forceinline__ void cp_wait2() {
    asm volatile("cp.async.wait_group 2;\n" ::: "memory");
}

// ---------------------------------------------------------------------------
// K0: compact token indices per expert + build dense tile list
// ---------------------------------------------------------------------------
__global__ void k0_compact(const int* __restrict__ inp_pos) {
    int tid = threadIdx.x;
    if (tid < P_EXP) g_cnt[tid] = 0;
    __syncthreads();
    for (int t = tid; t < T_TOK; t += blockDim.x) {
        int p = inp_pos[t];
        if (p < P_EXP) {
            int slot = atomicAdd(&g_cnt[p], 1);
            g_list[p][slot] = t;
        }
    }
    __syncthreads();
    if (tid == 0) {
        int n = 0;
        for (int p = 0; p < P_EXP; p++) {
            int c = g_cnt[p];
            for (int mt = 0; mt * TBM < c; mt++)
                g_tiles[n++] = make_int2(p, mt);
        }
        g_ntile = n;
    }
}

// ---------------------------------------------------------------------------
// Tensor GEMM: 3xTF32, 4-stage cp.async, split-K=4, dense tile list.
// grid = (nt, tile<=MAXT, kz=SPK)
// MODE 0: partial logits (no bias)   A=ctx[T,768],  B=dec_W
// MODE 1: partial embedding mix      A=spt[T,1024], B=gathered emb rows
// Block 32x64, 128 threads (4 warps, 2x2 of m16n32).
// ---------------------------------------------------------------------------
template <int MODE>
__global__ __launch_bounds__(128) void gemm_mma(
    const float* __restrict__ A_in,
    const float* __restrict__ B0,      // dec_W | psr_w
    const float* __restrict__ B1,      // -     | atk_w
    const int*   __restrict__ words,
    float*       __restrict__ out_part)
{
    const int tix = blockIdx.y;
    if (tix >= g_ntile) return;
    const int2 tile = g_tiles[tix];
    const int p  = tile.x;
    const int mt = tile.y;
    const int kz = blockIdx.z;
    const int nt = blockIdx.x;
    const int cnt = g_cnt[p];

    constexpr int KDIM = (MODE == 0) ? HS : M_SUB;
    constexpr int KH   = KDIM / SPK;     // 192 | 256
    constexpr int NIT  = KH / TBK;       // 12  | 16
    const int kbeg = kz * KH;

    __shared__ int toks[TBM];
    __shared__ __align__(16) float As[STG][TBM][ARS];
    __shared__ __align__(16) float Bs[STG][TBK][BRS];

    const int tid = threadIdx.x;
    if (tid < TBM) {
        int r = mt * TBM + tid;
        toks[tid] = (r < cnt) ? g_list[p][r] : -1;
    }
    __syncthreads();

    // loader roles
    const int am = tid >> 2;
    const int aq = tid & 3;
    const int br = tid >> 3;
    const int bc = tid & 7;

    const int atok = toks[am];
    const float* Arow = A_in + (size_t)(atok < 0 ? 0 : atok) * KDIM + kbeg;

    const float* Bp = nullptr;
    const float* tab = nullptr;
    const int* wp = nullptr;
    int dbase = 0;
    if (MODE == 0) {
        Bp = B0 + (size_t)p * HS * M_SUB + (size_t)kbeg * M_SUB + nt * TBN;
    } else {
        const int cbase0 = nt * TBN;
        tab   = (cbase0 < D_EMB) ? B0 : B1;
        dbase = (cbase0 < D_EMB) ? cbase0 : (cbase0 - D_EMB);
        wp    = words + p * M_SUB + kbeg;
    }

    const uint32_t sA = (uint32_t)__cvta_generic_to_shared(&As[0][0][0]);
    const uint32_t sB = (uint32_t)__cvta_generic_to_shared(&Bs[0][0][0]);
    const uint32_t aOK = (atok >= 0) ? 16u : 0u;
    const uint32_t adst = (uint32_t)(am * ARS + aq * 4) * 4u;
    const uint32_t bdst0 = (uint32_t)(br * BRS + bc * 4) * 4u;
    const uint32_t bdst1 = bdst0 + 128u;

    auto issue_stage = [&](int s, int k0) {
        cp16(sA + s * (TBM * ARS * 4) + adst, Arow + k0 + aq * 4, aOK);
        if (MODE == 0) {
            const float* row = Bp + (size_t)(k0 + br) * M_SUB;
            cp16(sB + s * (TBK * BRS * 4) + bdst0, row + bc * 4, 16);
            cp16(sB + s * (TBK * BRS * 4) + bdst1, row + (bc + 8) * 4, 16);
        } else {
            int w = __ldg(&wp[k0 + br]);
            const float* row = tab + (size_t)w * D_EMB + dbase;
            cp16(sB + s * (TBK * BRS * 4) + bdst0, row + bc * 4, 16);
            cp16(sB + s * (TBK * BRS * 4) + bdst1, row + (bc + 8) * 4, 16);
        }
        cp_commit();
    };

    // compute coordinates
    const int lane = tid & 31;
    const int wid  = tid >> 5;
    const int g = lane >> 2;
    const int t = lane & 3;
    const int r0w = (wid & 1) * 16;
    const int c0w = (wid >> 1) * 32;
    const int ra0 = r0w + g, ra1 = r0w + g + 8;

    float d[4][4] = {};

    issue_stage(0, 0);
    issue_stage(1, TBK);
    issue_stage(2, 2 * TBK);

    for (int it = 0; it < NIT; it++) {
        const int cur = it & (STG - 1);
        cp_wait2();
        __syncthreads();

        #pragma unroll
        for (int ko8 = 0; ko8 < 2; ko8++) {
            const int kk = ko8 * 8 + t;
            float af0 = As[cur][ra0][kk];
            float af1 = As[cur][ra1][kk];
            float af2 = As[cur][ra0][kk + 4];
            float af3 = As[cur][ra1][kk + 4];
            uint32_t ah0, al0, ah1, al1, ah2, al2, ah3, al3;
            split2(af0, ah0, al0);
            split2(af1, ah1, al1);
            split2(af2, ah2, al2);
            split2(af3, ah3, al3);
            #pragma unroll
            for (int j = 0; j < 4; j++) {
                const int n = c0w + 8 * j + g;
                float bf0 = Bs[cur][kk][n];
                float bf1 = Bs[cur][kk + 4][n];
                uint32_t bh0, bl0, bh1, bl1;
                split2(bf0, bh0, bl0);
                split2(bf1, bh1, bl1);
                mma_tf32(d[j], ah0, ah1, ah2, ah3, bh0, bh1);
                mma_tf32(d[j], ah0, ah1, ah2, ah3, bl0, bl1);
                mma_tf32(d[j], al0, al1, al2, al3, bh0, bh1);
            }
        }

        if (it + 3 < NIT) issue_stage((it + 3) & (STG - 1), (it + 3) * TBK);
        else cp_commit();
        __syncthreads();
    }

    // epilogue: write partial to the kz slice (combined column layout)
    float* outp = out_part + (size_t)kz * T_TOK * M_SUB;
    const int tok0 = toks[ra0];
    const int tok1 = toks[ra1];
    #pragma unroll
    for (int j = 0; j < 4; j++) {
        const int gcol = nt * TBN + c0w + 8 * j + 2 * t;
        if (tok0 >= 0)
            *reinterpret_cast<float2*>(&outp[(size_t)tok0 * M_SUB + gcol]) =
                make_float2(d[j][0], d[j][1]);
        if (tok1 >= 0)
            *reinterpret_cast<float2*>(&outp[(size_t)tok1 * M_SUB + gcol]) =
                make_float2(d[j][2], d[j][3]);
    }
}

// ---------------------------------------------------------------------------
// Block reductions (256 threads)
// ---------------------------------------------------------------------------
__device__ __forceinline__ float blockMax256(float v, volatile float* red, int tid) {
    int lane = tid & 31;
    #pragma unroll
    for (int o = 16; o > 0; o >>= 1)
        v = fmaxf(v, __shfl_xor_sync(0xffffffffu, v, o));
    __syncthreads();
    if (lane == 0) red[tid >> 5] = v;
    __syncthreads();
    float r = red[0];
    #pragma unroll
    for (int i = 1; i < 8; i++) r = fmaxf(r, red[i]);
    return r;
}

__device__ __forceinline__ float blockSum256(float v, volatile float* red, int tid) {
    int lane = tid & 31;
    #pragma unroll
    for (int o = 16; o > 0; o >>= 1)
        v += __shfl_xor_sync(0xffffffffu, v, o);
    __syncthreads();
    if (lane == 0) red[tid >> 5] = v;
    __syncthreads();
    float r = red[0];
    #pragma unroll
    for (int i = 1; i < 8; i++) r += red[i];
    return r;
}

__device__ __forceinline__ void blockArgMax256(float& v, int& idx,
                                               volatile float* red, volatile int* redi,
                                               int tid) {
    int lane = tid & 31;
    #pragma unroll
    for (int o = 16; o > 0; o >>= 1) {
        float ov = __shfl_xor_sync(0xffffffffu, v, o);
        int   oi = __shfl_xor_sync(0xffffffffu, idx, o);
        if (ov > v || (ov == v && oi < idx)) { v = ov; idx = oi; }
    }
    __syncthreads();
    if (lane == 0) { red[tid >> 5] = v; redi[tid >> 5] = idx; }
    __syncthreads();
    float bv = red[0]; int bi = redi[0];
    #pragma unroll
    for (int i = 1; i < 8; i++) {
        float ov = red[i]; int oi = redi[i];
        if (ov > bv || (ov == bv && oi < bi)) { bv = ov; bi = oi; }
    }
    v = bv; idx = bi;
}

// ---------------------------------------------------------------------------
// K2: combines 4 logit partials (+bias), then row ops; writes spt
// ---------------------------------------------------------------------------
__global__ __launch_bounds__(256) void k2_row(const int* __restrict__ inp_word,
                                              const int* __restrict__ inp_pos,
                                              const int* __restrict__ inp_mask,
                                              const float* __restrict__ u_gum,
                                              const int* __restrict__ words,
                                              const float* __restrict__ psr_w,
                                              const float* __restrict__ atk_w,
                                              const float* __restrict__ dec_b,
                                              float* __restrict__ out) {
    const int t   = blockIdx.x;
    const int tid = threadIdx.x;
    const int w0  = inp_word[t];
    const int p   = inp_pos[t];
    const bool mk = inp_mask[t] != 0;

    if (p >= P_EXP) {
        if (tid == 0) {
            out[OFF_WORD + t] = (float)w0;
            out[OFF_CPY + t]  = mk ? 1.0f : 0.0f;
            out[OFF_OBF + t]  = 0.0f;
            out[OFF_PRI + t]  = 0.0f;
        }
        const float4* ps = (const float4*)(psr_w + (size_t)w0 * D_EMB);
        const float4* as = (const float4*)(atk_w + (size_t)w0 * D_EMB);
        float4* po = (float4*)(out + OFF_PSR + (size_t)t * D_EMB);
        float4* ao = (float4*)(out + OFF_ATK + (size_t)t * D_EMB);
        for (int d = tid; d < D_EMB / 4; d += 256) { po[d] = ps[d]; ao[d] = as[d]; }
        return;
    }

    __shared__ float red[8];
    __shared__ int   redi[8];

    const float4* bb = (const float4*)(dec_b + (size_t)p * M_SUB);
    const float4* uv = (const float4*)(u_gum + (size_t)t * M_SUB);
    float4* rowv = (float4*)(g_spt + (size_t)t * M_SUB);

    float4 bi = bb[tid], uu4 = uv[tid];
    float l[4] = {bi.x, bi.y, bi.z, bi.w};
    #pragma unroll
    for (int kz = 0; kz < SPK; kz++) {
        const float4 pv = ((const float4*)(g_lg_part +
            (size_t)kz * T_TOK * M_SUB + (size_t)t * M_SUB))[tid];
        l[0] += pv.x; l[1] += pv.y; l[2] += pv.z; l[3] += pv.w;
    }

    float u4[4] = {uu4.x, uu4.y, uu4.z, uu4.w};
    float z[4];
    #pragma unroll
    for (int k = 0; k < 4; k++) {
        float uu = fminf(fmaxf(u4[k], 1e-6f), 1.0f - 1e-6f);
        z[k] = l[k] - logf(-logf(uu));
    }

    float m1 = fmaxf(fmaxf(l[0], l[1]), fmaxf(l[2], l[3]));
    m1 = blockMax256(m1, red, tid);
    float s1 = 0.0f;
    #pragma unroll
    for (int k = 0; k < 4; k++) s1 += expf(l[k] - m1);
    s1 = blockSum256(s1, red, tid);
    const float lse = m1 + logf(s1);

    float se = 0.0f;
    #pragma unroll
    for (int k = 0; k < 4; k++) {
        float ps = l[k] - lse;
        se += ps * expf(ps);
    }
    se = blockSum256(se, red, tid);
    if (tid == 0) g_negent[t] = -se;

    float mv = z[0]; int midx = tid * 4;
    #pragma unroll
    for (int k = 1; k < 4; k++) {
        if (z[k] > mv) { mv = z[k]; midx = tid * 4 + k; }
    }
    blockArgMax256(mv, midx, red, redi, tid);

    float s2 = 0.0f;
    #pragma unroll
    for (int k = 0; k < 4; k++) s2 += expf(z[k] - mv);
    s2 = blockSum256(s2, red, tid);
    const float inv = 1.0f / s2;
    float4 sv;
    sv.x = expf(z[0] - mv) * inv;
    sv.y = expf(z[1] - mv) * inv;
    sv.z = expf(z[2] - mv) * inv;
    sv.w = expf(z[3] - mv) * inv;
    rowv[tid] = sv;

    if (tid == 0) {
        int aw = words[p * M_SUB + midx];
        out[OFF_WORD + t] = (float)aw;
        out[OFF_CPY + t]  = (aw == w0 && mk) ? 1.0f : 0.0f;
        out[OFF_OBF + t]  = 1.0f;
        out[OFF_PRI + t]  = (p < 4) ? 1.0f : 0.0f;
    }
}

// ---------------------------------------------------------------------------
// K5: combine 4 embedding partials into out (target tokens only)
// ---------------------------------------------------------------------------
__global__ __launch_bounds__(256) void k5_combine(const int* __restrict__ inp_pos,
                                                  float* __restrict__ out) {
    const int t = blockIdx.x;
    if (inp_pos[t] >= P_EXP) return;
    const int tid = threadIdx.x;
    float4 v = make_float4(0.f, 0.f, 0.f, 0.f);
    #pragma unroll
    for (int kz = 0; kz < SPK; kz++) {
        const float4 pv = ((const float4*)(g_em_part +
            (size_t)kz * T_TOK * M_SUB + (size_t)t * M_SUB))[tid];
        v.x += pv.x; v.y += pv.y; v.z += pv.z; v.w += pv.w;
    }
    const int col = tid * 4;
    if (col < D_EMB)
        *((float4*)(out + OFF_PSR + (size_t)t * D_EMB + col)) = v;
    else
        *((float4*)(out + OFF_ATK + (size_t)t * D_EMB + col - D_EMB)) = v;
}

// ---------------------------------------------------------------------------
// K4: deterministic entropy finalize
// ---------------------------------------------------------------------------
__global__ void k4_ent(const int* __restrict__ inp_pos, float* __restrict__ out) {
    __shared__ float sh[256];
    __shared__ int   shc[256];
    __shared__ float ent_s;
    const int tid = threadIdx.x;
    if (tid == 0) ent_s = 0.0f;

    for (int p = 0; p < P_EXP; p++) {
        float s = 0.0f; int c = 0;
        for (int t = tid; t < T_TOK; t += 256) {
            if (inp_pos[t] == p) { s += g_negent[t]; c++; }
        }
        sh[tid] = s; shc[tid] = c;
        __syncthreads();
        for (int o = 128; o > 0; o >>= 1) {
            if (tid < o) { sh[tid] += sh[tid + o]; shc[tid] += shc[tid + o]; }
            __syncthreads();
        }
        if (tid == 0 && shc[0] > 0)
            ent_s += sh[0] / ((float)shc[0] * (float)M_SUB);
        __syncthreads();
    }
    if (tid == 0) out[OFF_ENT] = -ent_s;
}

// ---------------------------------------------------------------------------
// Entry point
// ---------------------------------------------------------------------------
extern "C" void kernel_launch(void* const* d_in, const int* in_sizes, int n_in,
                              void* d_out, int out_size) {
    const int*      inp_word = (const int*)d_in[0];
    const int*      inp_pos  = (const int*)d_in[1];
    const int*      inp_mask = (const int*)d_in[2];   // JAX bool -> int32
    const float*    ctx      = (const float*)d_in[3];
    const float*    dec_W    = (const float*)d_in[4];
    const float*    dec_b    = (const float*)d_in[5];
    const float*    psr_w    = (const float*)d_in[6];
    const float*    atk_w    = (const float*)d_in[7];
    const int*      words    = (const int*)d_in[8];
    const float*    u_gum    = (const float*)d_in[9];
    float*          out      = (float*)d_out;

    (void)in_sizes; (void)n_in; (void)out_size;

    static float* spt_ptr = nullptr;
    static float* lg_part = nullptr;
    static float* em_part = nullptr;
    if (spt_ptr == nullptr) {
        cudaGetSymbolAddress((void**)&spt_ptr, g_spt);
        cudaGetSymbolAddress((void**)&lg_part, g_lg_part);
        cudaGetSymbolAddress((void**)&em_part, g_em_part);
    }

    k0_compact<<<1, 256>>>(inp_pos);
    gemm_mma<0><<<dim3(M_SUB / TBN, MAXT, SPK), 128>>>(
        ctx, dec_W, nullptr, words, lg_part);
    k2_row<<<T_TOK, 256>>>(inp_word, inp_pos, inp_mask, u_gum, words,
                           psr_w, atk_w, dec_b, out);
    gemm_mma<1><<<dim3((2 * D_EMB) / TBN, MAXT, SPK), 128>>>(
        spt_ptr, psr_w, atk_w, words, em_part);
    k5_combine<<<T_TOK, 256>>>(inp_pos, out);
    k4_ent<<<1, 256>>>(inp_pos, out);
}